// round 15
// baseline (speedup 1.0000x reference)
#include <cuda_runtime.h>
#include <cuda_fp16.h>
#include <cstdint>
#include <cstddef>

#define HH   200
#define WW   200
#define NQ   40000
#define DD   256

__device__ float g_vproj[(size_t)2 * NQ * DD];   // fp16 payload
__device__ float g_off  [(size_t)NQ * 128];
__device__ float g_aw   [(size_t)NQ * 64];
__device__ float g_samp [(size_t)NQ * DD];       // fp16 payload

// ---------------------------------------------------------------------------
// helpers
// ---------------------------------------------------------------------------
__device__ __forceinline__ uint32_t smem_u32(const void* p) {
    uint32_t a;
    asm("{ .reg .u64 t; cvta.to.shared.u64 t, %1; cvt.u32.u64 %0, t; }"
        : "=r"(a) : "l"(p));
    return a;
}
__device__ __forceinline__ uint2 cvt_h4(float4 v) {
    __half2 h01 = __floats2half2_rn(v.x, v.y);
    __half2 h23 = __floats2half2_rn(v.z, v.w);
    uint2 r;
    r.x = *reinterpret_cast<uint32_t*>(&h01);
    r.y = *reinterpret_cast<uint32_t*>(&h23);
    return r;
}
__device__ __forceinline__ void mma_f16(float* c, const uint32_t* a, const uint32_t* b) {
    asm volatile(
        "mma.sync.aligned.m16n8k16.row.col.f32.f16.f16.f32 "
        "{%0,%1,%2,%3}, {%4,%5,%6,%7}, {%8,%9}, {%0,%1,%2,%3};"
        : "+f"(c[0]), "+f"(c[1]), "+f"(c[2]), "+f"(c[3])
        : "r"(a[0]), "r"(a[1]), "r"(a[2]), "r"(a[3]), "r"(b[0]), "r"(b[1]));
}
__device__ __forceinline__ void ldm_x4(uint32_t* r, uint32_t a) {
    asm volatile("ldmatrix.sync.aligned.m8n8.x4.shared.b16 {%0,%1,%2,%3}, [%4];"
        : "=r"(r[0]), "=r"(r[1]), "=r"(r[2]), "=r"(r[3]) : "r"(a));
}
#define BAR_SYNC(id)   asm volatile("bar.sync %0, 256;"   :: "r"(id) : "memory")
#define BAR_ARRIVE(id) asm volatile("bar.arrive %0, 256;" :: "r"(id) : "memory")

// ---------------------------------------------------------------------------
// Warp-specialized plain-fp16 HMMA GEMM — 256 threads, 2 CTAs/SM.
// Warps 0-3 consumers (2m x 2n, warp tile 64x32), warps 4-7 producers
// (double-reg-staged LDG -> cvt -> STS). 3-stage smem ring, K chunks of 32,
// KP=40 pad. Block tile 128 x 64.
// DUAL: A = concat(A0,A1) fp32 (stride 256 each, KTOT=512); out col (global)
// c<128 -> C0 (stride 128, bias0), else -> C1 (stride 64, bias1).
// HOUT: C0 is __half* (stride 256). HIN: A0 is __half* (stride KTOT).
// ---------------------------------------------------------------------------
template<int DUAL, int KTOT, int HOUT, int HIN>
__global__ void __launch_bounds__(256, 2)
hmma_gemm(const float* __restrict__ A0, const float* __restrict__ A1,
          const float* __restrict__ B0, const float* __restrict__ B1,
          const float* __restrict__ bias0, const float* __restrict__ bias1,
          const float* __restrict__ addend,
          float* __restrict__ C0, float* __restrict__ C1, int M)
{
    constexpr int KP  = 40;                     // padded row: 80 B
    constexpr int NCH = KTOT / 32;
    constexpr int S   = 3;                      // ring stages
    constexpr uint32_t A_OFF  = 0;
    constexpr uint32_t B_OFF  = 128u * KP * 2;              // 10240
    constexpr uint32_t SSTAGE = B_OFF + 64u * KP * 2;       // 15360

    extern __shared__ char smc[];
    const uint32_t sb = smem_u32(smc);

    const int tid = threadIdx.x;
    const int wid = tid >> 5, lane = tid & 31;
    const int brow = blockIdx.y * 128;
    const int bcol = blockIdx.x * 64;

    if (wid < 4) {
        // ================= CONSUMERS (2m x 2n) =================
        const int g = lane >> 2, t = lane & 3;
        const int warp_m = wid >> 1, warp_n = wid & 1;

        float acc[4][4][4];
        #pragma unroll
        for (int i = 0; i < 4; i++)
            #pragma unroll
            for (int j = 0; j < 4; j++)
                #pragma unroll
                for (int k = 0; k < 4; k++) acc[i][j][k] = 0.f;

        const uint32_t aFrag = sb + A_OFF
            + (uint32_t)(warp_m * 64 + (lane & 15)) * (KP * 2)
            + (uint32_t)((lane >> 4) << 4);
        const uint32_t bFragX4 = sb + B_OFF
            + (uint32_t)(warp_n * 32 + (lane >> 4) * 8 + (lane & 7)) * (KP * 2)
            + (uint32_t)(((lane >> 3) & 1) << 4);

        uint32_t stBase = 0;
        for (int ch = 0; ch < NCH; ch++) {
            int s = ch % S;
            BAR_SYNC(1 + s);
            #pragma unroll
            for (int ks = 0; ks < 2; ks++) {
                uint32_t Bf[4][2];
                #pragma unroll
                for (int ntp = 0; ntp < 2; ntp++) {
                    uint32_t addr = bFragX4 + stBase
                        + (uint32_t)(ntp * 16 * KP * 2) + (uint32_t)(ks * 32);
                    uint32_t r[4];
                    ldm_x4(r, addr);
                    Bf[2*ntp][0] = r[0]; Bf[2*ntp][1] = r[1];
                    Bf[2*ntp+1][0] = r[2]; Bf[2*ntp+1][1] = r[3];
                }
                #pragma unroll
                for (int mt = 0; mt < 4; mt++) {
                    uint32_t Af[4];
                    uint32_t aa = aFrag + stBase
                        + (uint32_t)(mt * 16 * KP * 2) + (uint32_t)(ks * 32);
                    ldm_x4(Af, aa);
                    #pragma unroll
                    for (int nt = 0; nt < 4; nt++)
                        mma_f16(acc[mt][nt], Af, Bf[nt]);
                }
            }
            BAR_ARRIVE(1 + S + s);
            stBase += SSTAGE;
            if (stBase == S * SSTAGE) stBase = 0;
        }

        // ---- epilogue ----
        #pragma unroll
        for (int mt = 0; mt < 4; mt++) {
            int r0 = brow + warp_m * 64 + mt * 16 + g;
            #pragma unroll
            for (int nt = 0; nt < 4; nt++) {
                int c = bcol + warp_n * 32 + nt * 8 + 2 * t;
                float2 v0 = make_float2(acc[mt][nt][0], acc[mt][nt][1]);
                float2 v1 = make_float2(acc[mt][nt][2], acc[mt][nt][3]);
                if (DUAL) {
                    if (c < 128) {
                        float2 b = *reinterpret_cast<const float2*>(bias0 + c);
                        v0.x += b.x; v0.y += b.y; v1.x += b.x; v1.y += b.y;
                        if (r0 < M)
                            *reinterpret_cast<float2*>(C0 + (size_t)r0 * 128 + c) = v0;
                        if (r0 + 8 < M)
                            *reinterpret_cast<float2*>(C0 + (size_t)(r0 + 8) * 128 + c) = v1;
                    } else {
                        int cc = c - 128;
                        float2 b = *reinterpret_cast<const float2*>(bias1 + cc);
                        v0.x += b.x; v0.y += b.y; v1.x += b.x; v1.y += b.y;
                        if (r0 < M)
                            *reinterpret_cast<float2*>(C1 + (size_t)r0 * 64 + cc) = v0;
                        if (r0 + 8 < M)
                            *reinterpret_cast<float2*>(C1 + (size_t)(r0 + 8) * 64 + cc) = v1;
                    }
                } else {
                    float2 b = *reinterpret_cast<const float2*>(bias0 + c);
                    v0.x += b.x; v0.y += b.y; v1.x += b.x; v1.y += b.y;
                    if (HOUT) {
                        __half* H = reinterpret_cast<__half*>(C0);
                        __half2 h0 = __floats2half2_rn(v0.x, v0.y);
                        __half2 h1 = __floats2half2_rn(v1.x, v1.y);
                        if (r0 < M)
                            *reinterpret_cast<uint32_t*>(H + (size_t)r0 * 256 + c) =
                                *reinterpret_cast<uint32_t*>(&h0);
                        if (r0 + 8 < M)
                            *reinterpret_cast<uint32_t*>(H + (size_t)(r0 + 8) * 256 + c) =
                                *reinterpret_cast<uint32_t*>(&h1);
                    } else {
                        if (r0 < M) {
                            if (addend) {
                                float2 a = *reinterpret_cast<const float2*>(
                                    addend + (size_t)r0 * 256 + c);
                                v0.x += a.x; v0.y += a.y;
                            }
                            *reinterpret_cast<float2*>(C0 + (size_t)r0 * 256 + c) = v0;
                        }
                        if (r0 + 8 < M) {
                            if (addend) {
                                float2 a = *reinterpret_cast<const float2*>(
                                    addend + (size_t)(r0 + 8) * 256 + c);
                                v1.x += a.x; v1.y += a.y;
                            }
                            *reinterpret_cast<float2*>(C0 + (size_t)(r0 + 8) * 256 + c) = v1;
                        }
                    }
                }
            }
        }
    } else {
        // ===== PRODUCERS: double-reg-staged software pipeline =====
        const int p = tid - 128;                  // 0..127
        const int bkq = p & 7, bnq = p >> 3;      // B task (one per thread)

        float4 rA[2][8];
        uint4  rA16[2][4];
        float4 rB[2][4];

        auto gload = [&](int ch, int buf) {
            const int k0 = ch * 32;
            if (HIN) {
                const __half* A16 = reinterpret_cast<const __half*>(A0);
                #pragma unroll
                for (int j = 0; j < 4; j++) {
                    int idx2 = p + j * 128;             // 0..511
                    int m = idx2 >> 2, kc = idx2 & 3;
                    int row = brow + m;
                    uint4 v = make_uint4(0, 0, 0, 0);
                    if (row < M)
                        v = *reinterpret_cast<const uint4*>(
                            A16 + (size_t)row * KTOT + k0 + kc * 8);
                    rA16[buf][j] = v;
                }
            } else {
                #pragma unroll
                for (int j = 0; j < 8; j++) {
                    int idx = p + j * 128;              // 0..1023
                    int m = idx >> 3, kq = idx & 7;
                    int row = brow + m;
                    float4 v = make_float4(0.f, 0.f, 0.f, 0.f);
                    if (row < M) {
                        int kg = k0 + kq * 4;
                        const float* src;
                        if (DUAL)
                            src = (kg < 256) ? (A0 + (size_t)row * 256 + kg)
                                             : (A1 + (size_t)row * 256 + (kg - 256));
                        else
                            src = A0 + (size_t)row * KTOT + kg;
                        v = *reinterpret_cast<const float4*>(src);
                    }
                    rA[buf][j] = v;
                }
            }
            #pragma unroll
            for (int i = 0; i < 4; i++) {
                int krow = k0 + bkq * 4 + i;
                int n = bcol + bnq * 4;
                const float* src;
                if (DUAL)
                    src = (n < 128) ? (B0 + (size_t)krow * 128 + n)
                                    : (B1 + (size_t)krow * 64 + (n - 128));
                else
                    src = B0 + (size_t)krow * 256 + n;
                rB[buf][i] = *reinterpret_cast<const float4*>(src);
            }
        };
        auto csstore = [&](int buf, uint32_t stBase) {
            char* base = smc + stBase;
            if (HIN) {
                #pragma unroll
                for (int j = 0; j < 4; j++) {
                    int idx2 = p + j * 128;
                    int m = idx2 >> 2, kc = idx2 & 3;
                    *reinterpret_cast<uint4*>(base + A_OFF + m * (KP*2) + kc * 16)
                        = rA16[buf][j];
                }
            } else {
                #pragma unroll
                for (int j = 0; j < 8; j++) {
                    int idx = p + j * 128;
                    int m = idx >> 3, kq = idx & 7;
                    uint2 av = cvt_h4(rA[buf][j]);
                    *reinterpret_cast<uint2*>(base + A_OFF + m * (KP*2) + kq * 8) = av;
                }
            }
            #pragma unroll
            for (int j = 0; j < 4; j++) {
                int n = bnq * 4 + j;
                float4 kv = make_float4((&rB[buf][0].x)[j], (&rB[buf][1].x)[j],
                                        (&rB[buf][2].x)[j], (&rB[buf][3].x)[j]);
                uint2 bb = cvt_h4(kv);
                *reinterpret_cast<uint2*>(base + B_OFF + n * (KP*2) + bkq * 8) = bb;
            }
        };

        gload(0, 0);
        uint32_t stBase = 0;
        for (int ch = 0; ch < NCH; ch++) {
            int s = ch % S;
            if (ch + 1 < NCH) gload(ch + 1, (ch + 1) & 1);  // LDGs in flight
            if (ch >= S) BAR_SYNC(1 + S + s);
            csstore(ch & 1, stBase);
            BAR_ARRIVE(1 + s);
            stBase += SSTAGE;
            if (stBase == S * SSTAGE) stBase = 0;
        }
    }
}

// ---------------------------------------------------------------------------
// Deformable sampling — vproj fp16 in, samp fp16 out (unchanged from R14).
// ---------------------------------------------------------------------------
__device__ __forceinline__ void accum_h(float4& acc, float w, uint2 u) {
    float2 p0 = __half22float2(*reinterpret_cast<__half2*>(&u.x));
    float2 p1 = __half22float2(*reinterpret_cast<__half2*>(&u.y));
    acc.x = fmaf(w, p0.x, acc.x); acc.y = fmaf(w, p0.y, acc.y);
    acc.z = fmaf(w, p1.x, acc.z); acc.w = fmaf(w, p1.y, acc.w);
}

__global__ void __launch_bounds__(256)
deform_sample_k(const float* __restrict__ vproj,
                const float* __restrict__ offr,
                const float* __restrict__ awr,
                const float* __restrict__ refp,
                float* __restrict__ samp)
{
    int wg   = (blockIdx.x * 256 + threadIdx.x) >> 5;
    int lane = threadIdx.x & 31;
    int q = wg >> 1;
    if (q >= NQ) return;
    int g = lane >> 3;
    int s = lane & 7;
    int h = ((wg & 1) << 2) | g;

    float rx = fmaf(refp[2*q+0], (float)WW, -0.5f);
    float ry = fmaf(refp[2*q+1], (float)HH, -0.5f);
    const float* offh = offr + (size_t)q*128 + h*16;
    const float* awh  = awr  + (size_t)q*64  + h*8;

    float4 acc = make_float4(0.f,0.f,0.f,0.f);

    #pragma unroll
    for (int nbq = 0; nbq < 2; nbq++) {
        float a0 = awh[nbq*4+0], a1 = awh[nbq*4+1];
        float a2 = awh[nbq*4+2], a3 = awh[nbq*4+3];
        float mx = fmaxf(fmaxf(a0,a1), fmaxf(a2,a3));
        float e0 = __expf(a0-mx), e1 = __expf(a1-mx);
        float e2 = __expf(a2-mx), e3 = __expf(a3-mx);
        float inv = 1.f / (e0+e1+e2+e3);
        float aws[4] = {e0*inv, e1*inv, e2*inv, e3*inv};

        const uint2* vb = reinterpret_cast<const uint2*>(vproj)
                        + ((size_t)nbq*NQ)*64 + h*8 + s;

        #pragma unroll
        for (int p = 0; p < 4; p++) {
            float x = rx + offh[nbq*8 + p*2 + 0];
            float y = ry + offh[nbq*8 + p*2 + 1];
            float xf = floorf(x), yf = floorf(y);
            float fx = x - xf, fy = y - yf;
            int x0 = (int)xf, y0 = (int)yf;
            int x1 = x0 + 1,  y1 = y0 + 1;

            float vx0 = ((unsigned)x0 < WW) ? 1.f : 0.f;
            float vx1 = ((unsigned)x1 < WW) ? 1.f : 0.f;
            float vy0 = ((unsigned)y0 < HH) ? 1.f : 0.f;
            float vy1 = ((unsigned)y1 < HH) ? 1.f : 0.f;
            int cx0 = min(max(x0,0), WW-1), cx1 = min(max(x1,0), WW-1);
            int cy0 = min(max(y0,0), HH-1), cy1 = min(max(y1,0), HH-1);

            float w   = aws[p];
            float gx1 = fx, gx0 = 1.f - fx;
            float gy1 = fy, gy0 = 1.f - fy;
            float w00 = w*gx0*gy0*vx0*vy0;
            float w01 = w*gx1*gy0*vx1*vy0;
            float w10 = w*gx0*gy1*vx0*vy1;
            float w11 = w*gx1*gy1*vx1*vy1;

            uint2 u00 = vb[(size_t)(cy0*WW + cx0) * 64];
            uint2 u01 = vb[(size_t)(cy0*WW + cx1) * 64];
            uint2 u10 = vb[(size_t)(cy1*WW + cx0) * 64];
            uint2 u11 = vb[(size_t)(cy1*WW + cx1) * 64];

            accum_h(acc, w00, u00);
            accum_h(acc, w01, u01);
            accum_h(acc, w10, u10);
            accum_h(acc, w11, u11);
        }
    }
    acc.x *= 0.5f; acc.y *= 0.5f; acc.z *= 0.5f; acc.w *= 0.5f;
    __half2 h0 = __floats2half2_rn(acc.x, acc.y);
    __half2 h1 = __floats2half2_rn(acc.z, acc.w);
    uint2 st;
    st.x = *reinterpret_cast<uint32_t*>(&h0);
    st.y = *reinterpret_cast<uint32_t*>(&h1);
    *reinterpret_cast<uint2*>(
        reinterpret_cast<__half*>(samp) + (size_t)q*DD + h*32 + s*4) = st;
}

// ---------------------------------------------------------------------------
extern "C" void kernel_launch(void* const* d_in, const int* in_sizes, int n_in,
                              void* d_out, int out_size)
{
    const float* query = (const float*)d_in[0];
    const float* value = (const float*)d_in[1];
    const float* refp  = (const float*)d_in[2];
    const float* W_v  = (const float*)d_in[4];
    const float* b_v  = (const float*)d_in[5];
    const float* W_so = (const float*)d_in[6];
    const float* b_so = (const float*)d_in[7];
    const float* W_aw = (const float*)d_in[8];
    const float* b_aw = (const float*)d_in[9];
    const float* W_o  = (const float*)d_in[10];
    const float* b_o  = (const float*)d_in[11];
    float* out = (float*)d_out;

    float *vproj, *offp, *awp, *sampp;
    cudaGetSymbolAddress((void**)&vproj, g_vproj);
    cudaGetSymbolAddress((void**)&offp,  g_off);
    cudaGetSymbolAddress((void**)&awp,   g_aw);
    cudaGetSymbolAddress((void**)&sampp, g_samp);

    // stage: (128 + 64) * 80 bytes; 3 stages = 46080 per CTA (2 CTAs/SM)
    constexpr int SMB = 3 * ((128 + 64) * 80);
    cudaFuncSetAttribute(hmma_gemm<0,256,1,0>,
        cudaFuncAttributeMaxDynamicSharedMemorySize, SMB);
    cudaFuncSetAttribute(hmma_gemm<1,512,0,0>,
        cudaFuncAttributeMaxDynamicSharedMemorySize, SMB);
    cudaFuncSetAttribute(hmma_gemm<0,256,0,1>,
        cudaFuncAttributeMaxDynamicSharedMemorySize, SMB);

    // GEMM1: vproj(fp16) = value @ W_v + b_v    (80000 x 256 x 256)
    hmma_gemm<0,256,1,0><<<dim3(4, 625), 256, SMB>>>(
        value, nullptr, W_v, nullptr, b_v, nullptr, nullptr,
        vproj, nullptr, 2*NQ);

    // GEMM2+3: [value0|query] @ {W_so,W_aw}     (40000 x {128,64} x 512)
    hmma_gemm<1,512,0,0><<<dim3(3, 313), 256, SMB>>>(
        value, query, W_so, W_aw, b_so, b_aw, nullptr,
        offp, awp, NQ);

    // Sampling (fp16 vproj -> fp16 samp)
    deform_sample_k<<<(NQ*2 + 7)/8, 256>>>(vproj, offp, awp, refp, sampp);

    // GEMM5: out = samp(fp16) @ W_o + b_o + query  (40000 x 256 x 256)
    hmma_gemm<0,256,0,1><<<dim3(4, 313), 256, SMB>>>(
        sampp, nullptr, W_o, nullptr, b_o, nullptr, query,
        out, nullptr, NQ);
}

// round 17
// speedup vs baseline: 1.8133x; 1.8133x over previous
#include <cuda_runtime.h>
#include <cuda_fp16.h>
#include <cstdint>
#include <cstddef>

#define HH   200
#define WW   200
#define NQ   40000
#define DD   256

__device__ float  g_vproj[(size_t)2 * NQ * DD];   // fp16 payload
__device__ float  g_off  [(size_t)NQ * 128];
__device__ float  g_aw   [(size_t)NQ * 64];
__device__ float  g_samp [(size_t)NQ * DD];       // fp16 payload
__device__ __half g_val16[(size_t)2 * NQ * DD];
__device__ __half g_q16  [(size_t)NQ * DD];
__device__ __half g_wv [256 * 256];
__device__ __half g_wo [256 * 256];
__device__ __half g_wso[128 * 512];
__device__ __half g_waw[ 64 * 512];

// ---------------------------------------------------------------------------
// helpers
// ---------------------------------------------------------------------------
__device__ __forceinline__ uint32_t smem_u32(const void* p) {
    uint32_t a;
    asm("{ .reg .u64 t; cvta.to.shared.u64 t, %1; cvt.u32.u64 %0, t; }"
        : "=r"(a) : "l"(p));
    return a;
}
__device__ __forceinline__ void mma_f16(float* c, const uint32_t* a, const uint32_t* b) {
    asm volatile(
        "mma.sync.aligned.m16n8k16.row.col.f32.f16.f16.f32 "
        "{%0,%1,%2,%3}, {%4,%5,%6,%7}, {%8,%9}, {%0,%1,%2,%3};"
        : "+f"(c[0]), "+f"(c[1]), "+f"(c[2]), "+f"(c[3])
        : "r"(a[0]), "r"(a[1]), "r"(a[2]), "r"(a[3]), "r"(b[0]), "r"(b[1]));
}
__device__ __forceinline__ void ldm_x4(uint32_t* r, uint32_t a) {
    asm volatile("ldmatrix.sync.aligned.m8n8.x4.shared.b16 {%0,%1,%2,%3}, [%4];"
        : "=r"(r[0]), "=r"(r[1]), "=r"(r[2]), "=r"(r[3]) : "r"(a));
}
__device__ __forceinline__ void ldm_x2(uint32_t* r, uint32_t a) {
    asm volatile("ldmatrix.sync.aligned.m8n8.x2.shared.b16 {%0,%1}, [%2];"
        : "=r"(r[0]), "=r"(r[1]) : "r"(a));
}
#define CP_ASYNC16(dst, src) \
    asm volatile("cp.async.ca.shared.global [%0], [%1], 16;" :: "r"(dst), "l"(src))
#define CP_COMMIT()  asm volatile("cp.async.commit_group;" ::: "memory")
#define CP_WAIT(n)   asm volatile("cp.async.wait_group %0;" :: "n"(n) : "memory")

// ---------------------------------------------------------------------------
// Pre-pass: fp32 -> fp16 (contiguous) and transposed weight convert.
// ---------------------------------------------------------------------------
__global__ void cvt16_k(const float* __restrict__ src, __half* __restrict__ dst,
                        size_t n) {
    size_t i = ((size_t)blockIdx.x * 256 + threadIdx.x) * 8;
    if (i < n) {
        float4 a = *reinterpret_cast<const float4*>(src + i);
        float4 b = *reinterpret_cast<const float4*>(src + i + 4);
        __half2 h0 = __floats2half2_rn(a.x, a.y);
        __half2 h1 = __floats2half2_rn(a.z, a.w);
        __half2 h2 = __floats2half2_rn(b.x, b.y);
        __half2 h3 = __floats2half2_rn(b.z, b.w);
        uint4 o;
        o.x = *reinterpret_cast<uint32_t*>(&h0);
        o.y = *reinterpret_cast<uint32_t*>(&h1);
        o.z = *reinterpret_cast<uint32_t*>(&h2);
        o.w = *reinterpret_cast<uint32_t*>(&h3);
        *reinterpret_cast<uint4*>(dst + i) = o;
    }
}
// dst[n*K+k] = (half)src[k*N+n]
__global__ void cvtT_k(const float* __restrict__ src, __half* __restrict__ dst,
                       int K, int N) {
    int idx = blockIdx.x * 256 + threadIdx.x;
    if (idx < K * N) {
        int n = idx / K, k = idx % K;
        dst[idx] = __float2half(src[(size_t)k * N + n]);
    }
}

// ---------------------------------------------------------------------------
// All-fp16 HMMA GEMM with cp.async multibuffer pipeline (depth S=4).
// 256 threads, 8 warps (2m x 4n), warp tile 64 x 8*NTN; block 128 x 32*NTN.
// All operands fp16 in GMEM: A [M][KTOT] row-major, B [N][KTOT] (pre-transposed).
// K chunks of 32, KP=40 pad.
// DUAL: A = concat(A0,A1) (row stride 256 each); output col (global)
// c<128 -> C0 fp32 (stride 128, bias0), else -> C1 fp32 (stride 64, bias1).
// HOUT: C0 is __half* (stride 256); else fp32 C0 stride 256 (+ addend).
// ---------------------------------------------------------------------------
template<int NTN, int DUAL, int KTOT, int HOUT>
__global__ void __launch_bounds__(256)
hmma_gemm(const __half* __restrict__ A0, const __half* __restrict__ A1,
          const __half* __restrict__ B0, const __half* __restrict__ B1,
          const float* __restrict__ bias0, const float* __restrict__ bias1,
          const float* __restrict__ addend,
          float* __restrict__ C0, float* __restrict__ C1, int M)
{
    constexpr int BN  = 32 * NTN;
    constexpr int KP  = 40;                       // padded row: 80 B
    constexpr int NCH = KTOT / 32;
    constexpr int S   = 4;
    constexpr uint32_t A_OFF  = 0;
    constexpr uint32_t B_OFF  = 128u * KP * 2;    // 10240
    constexpr uint32_t SSTAGE = B_OFF + (uint32_t)BN * KP * 2;

    extern __shared__ char smc[];
    const uint32_t sb = smem_u32(smc);

    const int tid = threadIdx.x;
    const int wid = tid >> 5, lane = tid & 31;
    const int brow = blockIdx.y * 128;
    const int bcol = blockIdx.x * BN;

    // ---- cp.async stage fill ----
    auto issue = [&](int ch, int st) {
        const uint32_t stb = sb + (uint32_t)st * SSTAGE;
        const int k0 = ch * 32;
        #pragma unroll
        for (int j = 0; j < 2; j++) {             // A: 512 16B pieces
            int idx = tid + j * 256;
            int m = idx >> 2, kc = idx & 3;
            int row = min(brow + m, M - 1);
            int kg = k0 + kc * 8;
            const __half* src;
            if (DUAL)
                src = (kg < 256) ? (A0 + (size_t)row * 256 + kg)
                                 : (A1 + (size_t)row * 256 + (kg - 256));
            else
                src = A0 + (size_t)row * KTOT + kg;
            CP_ASYNC16(stb + A_OFF + (uint32_t)(m * 80 + kc * 16), src);
        }
        #pragma unroll
        for (int j = 0; j < 2; j++) {             // B: BN*4 pieces
            int idx = tid + j * 256;
            if (NTN == 4 || idx < BN * 4) {
                int n = idx >> 2, kc = idx & 3;
                int kg = k0 + kc * 8;
                int gn = bcol + n;                // GLOBAL output column (R16 bugfix)
                const __half* src;
                if (DUAL)
                    src = (gn < 128) ? (B0 + (size_t)gn * 512 + kg)
                                     : (B1 + (size_t)(gn - 128) * 512 + kg);
                else
                    src = B0 + (size_t)gn * KTOT + kg;
                CP_ASYNC16(stb + B_OFF + (uint32_t)(n * 80 + kc * 16), src);
            }
        }
    };

    // ---- consumer state ----
    const int g = lane >> 2, t = lane & 3;
    const int warp_m = wid >> 2, warp_n = wid & 3;

    float acc[4][NTN][4];
    #pragma unroll
    for (int i = 0; i < 4; i++)
        #pragma unroll
        for (int j = 0; j < NTN; j++)
            #pragma unroll
            for (int k = 0; k < 4; k++) acc[i][j][k] = 0.f;

    const uint32_t aFrag = sb + A_OFF
        + (uint32_t)(warp_m * 64 + (lane & 15)) * (KP * 2)
        + (uint32_t)((lane >> 4) << 4);
    const uint32_t bFragX4 = sb + B_OFF
        + (uint32_t)(warp_n * 8 * NTN + (lane >> 4) * 8 + (lane & 7)) * (KP * 2)
        + (uint32_t)(((lane >> 3) & 1) << 4);
    const uint32_t bFragX2 = sb + B_OFF
        + (uint32_t)(warp_n * 8 * NTN + (NTN - 1) * 8 + (lane & 7)) * (KP * 2)
        + (uint32_t)(((lane >> 3) & 1) << 4);

    // ---- prologue: fill S-1 stages ----
    #pragma unroll
    for (int s = 0; s < S - 1; s++) {
        if (s < NCH) issue(s, s);
        CP_COMMIT();
    }

    // ---- main loop ----
    for (int ch = 0; ch < NCH; ch++) {
        int pre = ch + S - 1;
        if (pre < NCH) issue(pre, pre % S);
        CP_COMMIT();
        CP_WAIT(S - 2);
        __syncthreads();

        const uint32_t stBase = (uint32_t)(ch % S) * SSTAGE;
        #pragma unroll
        for (int ks = 0; ks < 2; ks++) {
            uint32_t Bf[NTN][2];
            #pragma unroll
            for (int ntp = 0; ntp < NTN / 2; ntp++) {
                uint32_t addr = bFragX4 + stBase
                    + (uint32_t)(ntp * 16 * KP * 2) + (uint32_t)(ks * 32);
                uint32_t r[4];
                ldm_x4(r, addr);
                Bf[2*ntp][0] = r[0]; Bf[2*ntp][1] = r[1];
                Bf[2*ntp+1][0] = r[2]; Bf[2*ntp+1][1] = r[3];
            }
            if (NTN & 1) {
                uint32_t addr = bFragX2 + stBase + (uint32_t)(ks * 32);
                ldm_x2(Bf[NTN-1], addr);
            }
            #pragma unroll
            for (int mt = 0; mt < 4; mt++) {
                uint32_t Af[4];
                uint32_t aa = aFrag + stBase
                    + (uint32_t)(mt * 16 * KP * 2) + (uint32_t)(ks * 32);
                ldm_x4(Af, aa);
                #pragma unroll
                for (int nt = 0; nt < NTN; nt++)
                    mma_f16(acc[mt][nt], Af, Bf[nt]);
            }
        }
        __syncthreads();
    }

    // ---- epilogue ----
    #pragma unroll
    for (int mt = 0; mt < 4; mt++) {
        int r0 = brow + warp_m * 64 + mt * 16 + g;
        #pragma unroll
        for (int nt = 0; nt < NTN; nt++) {
            int c = bcol + warp_n * 8 * NTN + nt * 8 + 2 * t;
            float2 v0 = make_float2(acc[mt][nt][0], acc[mt][nt][1]);
            float2 v1 = make_float2(acc[mt][nt][2], acc[mt][nt][3]);
            if (DUAL) {
                if (c < 128) {
                    float2 b = *reinterpret_cast<const float2*>(bias0 + c);
                    v0.x += b.x; v0.y += b.y; v1.x += b.x; v1.y += b.y;
                    if (r0 < M)
                        *reinterpret_cast<float2*>(C0 + (size_t)r0 * 128 + c) = v0;
                    if (r0 + 8 < M)
                        *reinterpret_cast<float2*>(C0 + (size_t)(r0 + 8) * 128 + c) = v1;
                } else {
                    int cc = c - 128;
                    float2 b = *reinterpret_cast<const float2*>(bias1 + cc);
                    v0.x += b.x; v0.y += b.y; v1.x += b.x; v1.y += b.y;
                    if (r0 < M)
                        *reinterpret_cast<float2*>(C1 + (size_t)r0 * 64 + cc) = v0;
                    if (r0 + 8 < M)
                        *reinterpret_cast<float2*>(C1 + (size_t)(r0 + 8) * 64 + cc) = v1;
                }
            } else {
                float2 b = *reinterpret_cast<const float2*>(bias0 + c);
                v0.x += b.x; v0.y += b.y; v1.x += b.x; v1.y += b.y;
                if (HOUT) {
                    __half* H = reinterpret_cast<__half*>(C0);
                    __half2 h0 = __floats2half2_rn(v0.x, v0.y);
                    __half2 h1 = __floats2half2_rn(v1.x, v1.y);
                    if (r0 < M)
                        *reinterpret_cast<uint32_t*>(H + (size_t)r0 * 256 + c) =
                            *reinterpret_cast<uint32_t*>(&h0);
                    if (r0 + 8 < M)
                        *reinterpret_cast<uint32_t*>(H + (size_t)(r0 + 8) * 256 + c) =
                            *reinterpret_cast<uint32_t*>(&h1);
                } else {
                    if (r0 < M) {
                        if (addend) {
                            float2 a = *reinterpret_cast<const float2*>(
                                addend + (size_t)r0 * 256 + c);
                            v0.x += a.x; v0.y += a.y;
                        }
                        *reinterpret_cast<float2*>(C0 + (size_t)r0 * 256 + c) = v0;
                    }
                    if (r0 + 8 < M) {
                        if (addend) {
                            float2 a = *reinterpret_cast<const float2*>(
                                addend + (size_t)(r0 + 8) * 256 + c);
                            v1.x += a.x; v1.y += a.y;
                        }
                        *reinterpret_cast<float2*>(C0 + (size_t)(r0 + 8) * 256 + c) = v1;
                    }
                }
            }
        }
    }
}

// ---------------------------------------------------------------------------
// Deformable sampling — vproj fp16 in, samp fp16 out (unchanged from R14).
// ---------------------------------------------------------------------------
__device__ __forceinline__ void accum_h(float4& acc, float w, uint2 u) {
    float2 p0 = __half22float2(*reinterpret_cast<__half2*>(&u.x));
    float2 p1 = __half22float2(*reinterpret_cast<__half2*>(&u.y));
    acc.x = fmaf(w, p0.x, acc.x); acc.y = fmaf(w, p0.y, acc.y);
    acc.z = fmaf(w, p1.x, acc.z); acc.w = fmaf(w, p1.y, acc.w);
}

__global__ void __launch_bounds__(256)
deform_sample_k(const float* __restrict__ vproj,
                const float* __restrict__ offr,
                const float* __restrict__ awr,
                const float* __restrict__ refp,
                float* __restrict__ samp)
{
    int wg   = (blockIdx.x * 256 + threadIdx.x) >> 5;
    int lane = threadIdx.x & 31;
    int q = wg >> 1;
    if (q >= NQ) return;
    int g = lane >> 3;
    int s = lane & 7;
    int h = ((wg & 1) << 2) | g;

    float rx = fmaf(refp[2*q+0], (float)WW, -0.5f);
    float ry = fmaf(refp[2*q+1], (float)HH, -0.5f);
    const float* offh = offr + (size_t)q*128 + h*16;
    const float* awh  = awr  + (size_t)q*64  + h*8;

    float4 acc = make_float4(0.f,0.f,0.f,0.f);

    #pragma unroll
    for (int nbq = 0; nbq < 2; nbq++) {
        float a0 = awh[nbq*4+0], a1 = awh[nbq*4+1];
        float a2 = awh[nbq*4+2], a3 = awh[nbq*4+3];
        float mx = fmaxf(fmaxf(a0,a1), fmaxf(a2,a3));
        float e0 = __expf(a0-mx), e1 = __expf(a1-mx);
        float e2 = __expf(a2-mx), e3 = __expf(a3-mx);
        float inv = 1.f / (e0+e1+e2+e3);
        float aws[4] = {e0*inv, e1*inv, e2*inv, e3*inv};

        const uint2* vb = reinterpret_cast<const uint2*>(vproj)
                        + ((size_t)nbq*NQ)*64 + h*8 + s;

        #pragma unroll
        for (int p = 0; p < 4; p++) {
            float x = rx + offh[nbq*8 + p*2 + 0];
            float y = ry + offh[nbq*8 + p*2 + 1];
            float xf = floorf(x), yf = floorf(y);
            float fx = x - xf, fy = y - yf;
            int x0 = (int)xf, y0 = (int)yf;
            int x1 = x0 + 1,  y1 = y0 + 1;

            float vx0 = ((unsigned)x0 < WW) ? 1.f : 0.f;
            float vx1 = ((unsigned)x1 < WW) ? 1.f : 0.f;
            float vy0 = ((unsigned)y0 < HH) ? 1.f : 0.f;
            float vy1 = ((unsigned)y1 < HH) ? 1.f : 0.f;
            int cx0 = min(max(x0,0), WW-1), cx1 = min(max(x1,0), WW-1);
            int cy0 = min(max(y0,0), HH-1), cy1 = min(max(y1,0), HH-1);

            float w   = aws[p];
            float gx1 = fx, gx0 = 1.f - fx;
            float gy1 = fy, gy0 = 1.f - fy;
            float w00 = w*gx0*gy0*vx0*vy0;
            float w01 = w*gx1*gy0*vx1*vy0;
            float w10 = w*gx0*gy1*vx0*vy1;
            float w11 = w*gx1*gy1*vx1*vy1;

            uint2 u00 = vb[(size_t)(cy0*WW + cx0) * 64];
            uint2 u01 = vb[(size_t)(cy0*WW + cx1) * 64];
            uint2 u10 = vb[(size_t)(cy1*WW + cx0) * 64];
            uint2 u11 = vb[(size_t)(cy1*WW + cx1) * 64];

            accum_h(acc, w00, u00);
            accum_h(acc, w01, u01);
            accum_h(acc, w10, u10);
            accum_h(acc, w11, u11);
        }
    }
    acc.x *= 0.5f; acc.y *= 0.5f; acc.z *= 0.5f; acc.w *= 0.5f;
    __half2 h0 = __floats2half2_rn(acc.x, acc.y);
    __half2 h1 = __floats2half2_rn(acc.z, acc.w);
    uint2 st;
    st.x = *reinterpret_cast<uint32_t*>(&h0);
    st.y = *reinterpret_cast<uint32_t*>(&h1);
    *reinterpret_cast<uint2*>(
        reinterpret_cast<__half*>(samp) + (size_t)q*DD + h*32 + s*4) = st;
}

// ---------------------------------------------------------------------------
extern "C" void kernel_launch(void* const* d_in, const int* in_sizes, int n_in,
                              void* d_out, int out_size)
{
    const float* query = (const float*)d_in[0];
    const float* value = (const float*)d_in[1];
    const float* refp  = (const float*)d_in[2];
    const float* W_v  = (const float*)d_in[4];
    const float* b_v  = (const float*)d_in[5];
    const float* W_so = (const float*)d_in[6];
    const float* b_so = (const float*)d_in[7];
    const float* W_aw = (const float*)d_in[8];
    const float* b_aw = (const float*)d_in[9];
    const float* W_o  = (const float*)d_in[10];
    const float* b_o  = (const float*)d_in[11];
    float* out = (float*)d_out;

    float *vproj, *offp, *awp, *sampp;
    __half *val16, *q16, *wv, *wo, *wso, *waw;
    cudaGetSymbolAddress((void**)&vproj, g_vproj);
    cudaGetSymbolAddress((void**)&offp,  g_off);
    cudaGetSymbolAddress((void**)&awp,   g_aw);
    cudaGetSymbolAddress((void**)&sampp, g_samp);
    cudaGetSymbolAddress((void**)&val16, g_val16);
    cudaGetSymbolAddress((void**)&q16,   g_q16);
    cudaGetSymbolAddress((void**)&wv,    g_wv);
    cudaGetSymbolAddress((void**)&wo,    g_wo);
    cudaGetSymbolAddress((void**)&wso,   g_wso);
    cudaGetSymbolAddress((void**)&waw,   g_waw);

    constexpr int SM4 = 4 * (128 * 80 + 128 * 80);  // 81920 (NTN=4)
    constexpr int SM3 = 4 * (128 * 80 + 96 * 80);   // 71680 (NTN=3)
    cudaFuncSetAttribute(hmma_gemm<4,0,256,1>,
        cudaFuncAttributeMaxDynamicSharedMemorySize, SM4);
    cudaFuncSetAttribute(hmma_gemm<3,1,512,0>,
        cudaFuncAttributeMaxDynamicSharedMemorySize, SM3);
    cudaFuncSetAttribute(hmma_gemm<4,0,256,0>,
        cudaFuncAttributeMaxDynamicSharedMemorySize, SM4);

    // ---- pre-pass: fp16 conversions ----
    cvt16_k<<<(int)(((size_t)2*NQ*DD/8 + 255)/256), 256>>>(value, val16, (size_t)2*NQ*DD);
    cvt16_k<<<(int)(((size_t)NQ*DD/8 + 255)/256), 256>>>(query, q16, (size_t)NQ*DD);
    cvtT_k<<<(256*256 + 255)/256, 256>>>(W_v,  wv,  256, 256);
    cvtT_k<<<(256*256 + 255)/256, 256>>>(W_o,  wo,  256, 256);
    cvtT_k<<<(512*128 + 255)/256, 256>>>(W_so, wso, 512, 128);
    cvtT_k<<<(512*64  + 255)/256, 256>>>(W_aw, waw, 512, 64);

    // GEMM1: vproj(fp16) = value16 @ wv^T + b_v   (80000 x 256 x 256)
    hmma_gemm<4,0,256,1><<<dim3(2, 625), 256, SM4>>>(
        val16, nullptr, wv, nullptr, b_v, nullptr, nullptr,
        vproj, nullptr, 2*NQ);

    // GEMM2+3: [value0|query]16 @ {wso,waw}^T     (40000 x {128,64} x 512)
    hmma_gemm<3,1,512,0><<<dim3(2, 313), 256, SM3>>>(
        val16, q16, wso, waw, b_so, b_aw, nullptr,
        offp, awp, NQ);

    // Sampling (fp16 vproj -> fp16 samp)
    deform_sample_k<<<(NQ*2 + 7)/8, 256>>>(vproj, offp, awp, refp, sampp);

    // GEMM5: out = samp16 @ wo^T + b_o + query    (40000 x 256 x 256)
    hmma_gemm<4,0,256,0><<<dim3(2, 313), 256, SM4>>>(
        reinterpret_cast<__half*>(sampp), nullptr, wo, nullptr, b_o, nullptr, query,
        out, nullptr, NQ);
}